// round 7
// baseline (speedup 1.0000x reference)
#include <cuda_runtime.h>
#include <float.h>
#include <math.h>

// CropRoi: f (4,64,32,32,32) f32; proposals (96,8) f32; out (96,64,7,7,7) f32.
// Box: c0 = max(floor((c-s/2)/4),0), c1 = min(ceil((c+s/2)/4),32); L in [2,13].
// Per-axis windows [i*L/7, ceil((i+1)L/7)) are 1..3 wide and in-range -> plain max.
//
// SINGLE kernel, SINGLE wave, no smem, no barriers: one warp per (n,c).
//  - box math inlined per warp (uniform; const-div by 7 -> mul/shift)
//  - lane = w: each f row is one aligned 128B line -> 1 wavefront per LDG
//  - per (i,j): fold the d,h window into a register acc (~1.7 rows),
//    then 3 clamped-tap shuffles resolve all 7 w-bins; lanes 0..6 store
//    7 consecutive floats (1 STG wavefront).
// 6144 warps = 1024 blocks x 192 threads ~= one wave on 148 SMs.

#define RBINS 7
#define FDIM 32

__global__ __launch_bounds__(192)
void crop_pool_kernel(const float* __restrict__ f,
                      const float* __restrict__ props,
                      float* __restrict__ out,
                      int nwarp)
{
    const int lane = threadIdx.x & 31;
    const int wg   = blockIdx.x * 6 + (threadIdx.x >> 5);
    if (wg >= nwarp) return;

    const int n = wg >> 6;     // proposal
    const int c = wg & 63;     // channel

    // proposals row: [b, score, cx, cy, cz, sx, sy, sz] -> two broadcast float4
    const float4 pa = __ldg((const float4*)(props + n * 8));
    const float4 pb = __ldg((const float4*)(props + n * 8) + 1);
    const int b = (int)pa.x;

    int c0d, Ld, c0h, Lh, c0w, Lw;
    {
        int lo = (int)floorf((pa.z - pb.y * 0.5f) * 0.25f);
        int hi = (int)ceilf ((pa.z + pb.y * 0.5f) * 0.25f);
        lo = max(lo, 0); hi = min(hi, FDIM); c0d = lo; Ld = hi - lo;
    }
    {
        int lo = (int)floorf((pa.w - pb.z * 0.5f) * 0.25f);
        int hi = (int)ceilf ((pa.w + pb.z * 0.5f) * 0.25f);
        lo = max(lo, 0); hi = min(hi, FDIM); c0h = lo; Lh = hi - lo;
    }
    {
        int lo = (int)floorf((pb.x - pb.w * 0.5f) * 0.25f);
        int hi = (int)ceilf ((pb.x + pb.w * 0.5f) * 0.25f);
        lo = max(lo, 0); hi = min(hi, FDIM); c0w = lo; Lw = hi - lo;
    }

    // w-bin taps for this lane (lanes 0..6 produce outputs; others just source)
    const int k  = min(lane, RBINS - 1);
    const int s  = (k * Lw) / RBINS;
    const int e  = ((k + 1) * Lw + RBINS - 1) / RBINS;
    const int t0 = c0w + s;
    const int t1 = c0w + min(s + 1, e - 1);
    const int t2 = c0w + e - 1;

    // h-bin bounds (box-relative), register arrays via full unroll
    int hs[RBINS], he[RBINS];
#pragma unroll
    for (int j = 0; j < RBINS; ++j) {
        hs[j] = (j * Lh) / RBINS;
        he[j] = ((j + 1) * Lh + RBINS - 1) / RBINS;
    }

    const float* base = f + (((size_t)((b << 6) + c)) << 15)
                          + (c0d << 10) + (c0h << 5) + lane;
    float* ob = out + (size_t)wg * 343 + lane;   // lane == k for stores

    for (int i = 0; i < RBINS; ++i) {
        const int ds = (i * Ld) / RBINS;
        const int de = ((i + 1) * Ld + RBINS - 1) / RBINS;
        const float* dbase = base + (ds << 10);

#pragma unroll
        for (int j = 0; j < RBINS; ++j) {
            float acc = -FLT_MAX;
            const float* rp0 = dbase + (hs[j] << 5);
            for (int d = ds; d < de; ++d) {
                const float* rp = rp0;
                for (int h = hs[j]; h < he[j]; ++h) {
                    acc = fmaxf(acc, *rp);       // full row: 1 wavefront
                    rp += FDIM;
                }
                rp0 += FDIM * FDIM;
            }
            // resolve all 7 w-bins: 3 clamped taps, duplicates harmless
            float g = fmaxf(fmaxf(__shfl_sync(0xFFFFFFFFu, acc, t0),
                                  __shfl_sync(0xFFFFFFFFu, acc, t1)),
                            __shfl_sync(0xFFFFFFFFu, acc, t2));
            if (lane < RBINS)
                ob[i * 49 + j * RBINS] = g;      // 7 consecutive floats
        }
    }
}

extern "C" void kernel_launch(void* const* d_in, const int* in_sizes, int n_in,
                              void* d_out, int out_size)
{
    const float* f     = (const float*)d_in[0];
    const float* props = (const float*)d_in[2];
    float* out = (float*)d_out;

    const int N = in_sizes[2] / 8;        // 96 proposals
    const int nwarp = N * 64;             // one warp per (n, c)
    const int blocks = (nwarp + 5) / 6;   // 6 warps (192 thr) per block

    crop_pool_kernel<<<blocks, 192>>>(f, props, out, nwarp);
}

// round 8
// speedup vs baseline: 2.1077x; 2.1077x over previous
#include <cuda_runtime.h>
#include <float.h>
#include <math.h>

// CropRoi: f (4,64,32,32,32) f32; proposals (96,8) f32; out (96,64,7,7,7) f32.
// Box: c0 = max(floor((c-s/2)/4),0), c1 = min(ceil((c+s/2)/4),32); L in [2,13].
// Adaptive windows per axis: size 1..3, always in-range -> plain max.
//
// Model result from R2..R7: the op is wave-transition bound (R2 = 8.3 waves
// x ~2.4K cyc) and worst-warp bound in single-wave layouts. Fix: persistent
// grid-stride kernel, 740 blocks (~5/SM, ~1 resident wave), each looping <=9
// independent iterations over (n,c) slots with stride 740. Heavy proposals
// spread across 64 distinct resident blocks; iterations have no barriers so
// their latency overlaps. Desc LDGs for all iterations prefetched upfront.

#define RBINS 7
#define NBINS 343
#define FDIM 32
#define MAXN 128
#define GRIDB 740
#define MAXIT 9          // GRIDB * MAXIT = 6660 >= 96*64

__device__ int g_desc[MAXN * NBINS];
__device__ int g_base[MAXN];

__global__ void precompute_kernel(const float* __restrict__ props)
{
    const int n = blockIdx.x;
    const int o = threadIdx.x;
    const float* p = props + n * 8;

    int c0[3], L[3];
#pragma unroll
    for (int ax = 0; ax < 3; ++ax) {
        const float ce = p[2 + ax], si = p[5 + ax];
        int lo = (int)floorf((ce - si * 0.5f) * 0.25f);
        int hi = (int)ceilf ((ce + si * 0.5f) * 0.25f);
        lo = max(lo, 0); hi = min(hi, FDIM);
        c0[ax] = lo;
        L[ax]  = max(hi - lo, 0);
    }

    if (o == 0) {
        const int b = (int)p[0];
        g_base[n] = ((b * 64) << 15) +
                    ((c0[0] * FDIM + c0[1]) * FDIM + c0[2]);
    }

    if (o < NBINS) {
        const int k = o % RBINS;
        const int j = (o / RBINS) % RBINS;
        const int i = o / (RBINS * RBINS);

        const int ds = (i * L[0]) / RBINS, de = ((i + 1) * L[0] + RBINS - 1) / RBINS;
        const int hs = (j * L[1]) / RBINS, he = ((j + 1) * L[1] + RBINS - 1) / RBINS;
        const int ws = (k * L[2]) / RBINS, we = ((k + 1) * L[2] + RBINS - 1) / RBINS;

        const int start = (ds * FDIM + hs) * FDIM + ws;               // 15 bits
        const int nd = de - ds - 1, nh = he - hs - 1, nw = we - ws - 1; // 0..2
        g_desc[n * NBINS + o] = start | (nd << 15) | (nh << 17) | (nw << 19);
    }
}

__global__ __launch_bounds__(352)
void pool_kernel(const float* __restrict__ f, float* __restrict__ out, int NC)
{
    const int tid = threadIdx.x;
    const bool act = tid < NBINS;

    // prefetch all iteration descriptors (independent LDGs, MLP ~ 9)
    int descs[MAXIT];
#pragma unroll
    for (int t = 0; t < MAXIT; ++t) {
        const int nc = blockIdx.x + t * GRIDB;
        descs[t] = (act && nc < NC) ? g_desc[(nc >> 6) * NBINS + tid] : -1;
    }

#pragma unroll
    for (int t = 0; t < MAXIT; ++t) {
        const int nc = blockIdx.x + t * GRIDB;
        if (!act || nc >= NC) continue;

        const int desc  = descs[t];
        const int start =  desc        & 0x7FFF;
        const int nd    = (desc >> 15) & 3;
        const int nh    = (desc >> 17) & 3;
        const int nw    = (desc >> 19) & 3;

        const float* base = f + g_base[nc >> 6] + ((nc & 63) << 15) + start;

        float m = -FLT_MAX;
        for (int d = 0; d <= nd; ++d)
            for (int h = 0; h <= nh; ++h) {
                const float* row = base + (d * FDIM + h) * FDIM;
                for (int w = 0; w <= nw; ++w)
                    m = fmaxf(m, row[w]);
            }

        out[(size_t)nc * NBINS + tid] = m;
    }
}

extern "C" void kernel_launch(void* const* d_in, const int* in_sizes, int n_in,
                              void* d_out, int out_size)
{
    const float* f     = (const float*)d_in[0];
    const float* props = (const float*)d_in[2];
    float* out = (float*)d_out;

    const int N  = in_sizes[2] / 8;   // 96
    const int NC = N * 64;            // 6144 (n,c) slots

    precompute_kernel<<<N, 352>>>(props);
    pool_kernel<<<GRIDB, 352>>>(f, out, NC);
}